// round 9
// baseline (speedup 1.0000x reference)
#include <cuda_runtime.h>
#include <math.h>

#define BATCH 512
#define HO 31
#define WO 31
#define HW 64
#define PLANE (HO * WO)              // 961
#define OUT_PER_B (12 * PLANE)       // 11532 floats = 2883 float4 per batch slab
#define NCHUNK (OUT_PER_B / 4)       // 2883

// Per-patch closed-form invariants of the quantum circuit:
//   S2 = sum p_i^2 ; D2 = signed sum (row sign (+,-,+,-), col sign (+,-,-,+))
//   dP = sum over pairs (i, i^12): rows 0<->3 and 1<->2, same column
// Output plane 3k+c = cA[plane]*D2/S2 + cB[plane]*dP/S2, coefficients from
// U3 of qubit 0 only (wires-1..3 unitary cancels: real input, wire-0 obs).
//
// One block per batch image: stage 16KB image -> compute 961 (Dl,dd) pairs ->
// write the 46KB contiguous output slab with aligned STG.128.

__global__ __launch_bounds__(256) void qconv_kernel(const float* __restrict__ x,
                                                    const float* __restrict__ w,
                                                    float* __restrict__ out) {
    __shared__ __align__(16) float img[HW * HW];     // 16 KB
    __shared__ __align__(16) float2 res[PLANE + 3];  // (Dl, dd) per patch (+pad)
    __shared__ float cA[12], cB[12];                 // per-plane coefficients

    const int tid = threadIdx.x;
    const int b = blockIdx.x;

    if (tid < 4) {
        const int k = tid;
        float th = w[k * 12 + 0], ph = w[k * 12 + 1], om = w[k * 12 + 2];
        float st, ct, spo, cpo, smp, cmp, sp, cp, som, com_;
        sincosf(th, &st, &ct);
        sincosf(ph, &sp, &cp);
        sincosf(ph + om, &spo, &cpo);
        sincosf(om - ph, &smp, &cmp);
        sincosf(om, &som, &com_);
        float c2 = 0.5f * (1.0f + ct);
        float s2 = 0.5f * (1.0f - ct);
        cA[3 * k + 0] = st * cp;                        // ex
        cB[3 * k + 0] = 2.0f * (c2 * cpo - s2 * cmp);
        cA[3 * k + 1] = st * sp;                        // ey
        cB[3 * k + 1] = 2.0f * (c2 * spo + s2 * smp);
        cA[3 * k + 2] = ct;                             // ez
        cB[3 * k + 2] = -2.0f * st * com_;
    }
    if (tid < 3) res[PLANE + tid] = make_float2(0.f, 0.f);  // pad for qm+3 reach

    // ---- phase 1: stage image (coalesced LDG.128, input read exactly once) ----
    const float4* src = reinterpret_cast<const float4*>(x + (size_t)b * (HW * HW));
    float4* dimg = reinterpret_cast<float4*>(img);
#pragma unroll
    for (int i = 0; i < 4; ++i)
        dimg[tid + i * 256] = src[tid + i * 256];
    __syncthreads();

    // ---- phase 2: per-patch invariants from smem ----
    for (int q = tid; q < PLANE; q += 256) {
        int ho = q / WO;
        int wo = q - ho * WO;
        const float* pr = img + (2 * ho) * HW + 2 * wo;

        float2 u0 = *reinterpret_cast<const float2*>(pr);
        float2 v0 = *reinterpret_cast<const float2*>(pr + 2);
        float2 u1 = *reinterpret_cast<const float2*>(pr + HW);
        float2 v1 = *reinterpret_cast<const float2*>(pr + HW + 2);
        float2 u2 = *reinterpret_cast<const float2*>(pr + 2 * HW);
        float2 v2 = *reinterpret_cast<const float2*>(pr + 2 * HW + 2);
        float2 u3 = *reinterpret_cast<const float2*>(pr + 3 * HW);
        float2 v3 = *reinterpret_cast<const float2*>(pr + 3 * HW + 2);

        float q0 = u0.x * u0.x + u0.y * u0.y + v0.x * v0.x + v0.y * v0.y;
        float q1 = u1.x * u1.x + u1.y * u1.y + v1.x * v1.x + v1.y * v1.y;
        float q2 = u2.x * u2.x + u2.y * u2.y + v2.x * v2.x + v2.y * v2.y;
        float q3 = u3.x * u3.x + u3.y * u3.y + v3.x * v3.x + v3.y * v3.y;
        float d0 = u0.x * u0.x - u0.y * u0.y - v0.x * v0.x + v0.y * v0.y;
        float d1 = u1.x * u1.x - u1.y * u1.y - v1.x * v1.x + v1.y * v1.y;
        float d2 = u2.x * u2.x - u2.y * u2.y - v2.x * v2.x + v2.y * v2.y;
        float d3 = u3.x * u3.x - u3.y * u3.y - v3.x * v3.x + v3.y * v3.y;
        float S = q0 + q1 + q2 + q3;
        float D = d0 - d1 + d2 - d3;                  // row signs (+,-,+,-)
        float P = u0.x * u3.x + u0.y * u3.y + v0.x * v3.x + v0.y * v3.y
                + u1.x * u2.x + u1.y * u2.y + v1.x * v2.x + v1.y * v2.y;
        float inv = 1.0f / S;                         // reference eps cancels
        res[q] = make_float2(D * inv, P * inv);
    }
    __syncthreads();

    // ---- phase 3: aligned STG.128 over the contiguous 46KB output slab ----
    float* ob = out + (size_t)b * OUT_PER_B;
    for (int j = tid; j < NCHUNK; j += 256) {
        int q0 = 4 * j;                               // slab float index of chunk
        int p0 = q0 / PLANE;
        int p3 = (q0 + 3) / PLANE;
        if (p0 == p3) {                               // whole chunk in one plane
            int qm = q0 - p0 * PLANE;                 // patch index of element 0
            float2 r0 = res[qm + 0];
            float2 r1 = res[qm + 1];
            float2 r2 = res[qm + 2];
            float2 r3 = res[qm + 3];
            float a = cA[p0], c = cB[p0];
            float4 o;
            o.x = a * r0.x + c * r0.y;
            o.y = a * r1.x + c * r1.y;
            o.z = a * r2.x + c * r2.y;
            o.w = a * r3.x + c * r3.y;
            *reinterpret_cast<float4*>(ob + q0) = o;  // slab base + 16B-mult offset
        } else {                                      // plane boundary (11 chunks)
#pragma unroll
            for (int e = 0; e < 4; ++e) {
                int idx = q0 + e;
                int pl = idx / PLANE;
                int qe = idx - pl * PLANE;
                float2 r = res[qe];
                ob[idx] = cA[pl] * r.x + cB[pl] * r.y;
            }
        }
    }
}

extern "C" void kernel_launch(void* const* d_in, const int* in_sizes, int n_in,
                              void* d_out, int out_size) {
    const float* x = (const float*)d_in[0];
    const float* w = (const float*)d_in[1];
    if (n_in >= 2 && in_sizes[0] == 48) {  // robustness: weights listed first
        x = (const float*)d_in[1];
        w = (const float*)d_in[0];
    }
    float* out = (float*)d_out;

    qconv_kernel<<<BATCH, 256>>>(x, w, out);
}

// round 10
// speedup vs baseline: 1.3732x; 1.3732x over previous
#include <cuda_runtime.h>
#include <math.h>

#define BATCH 512
#define HO 31
#define WO 31
#define HW 64
#define PLANE (HO * WO)

// Per-patch closed-form invariants of the quantum circuit:
//   S2 = sum p_i^2 ; D2 = signed sum (row sign (+,-,+,-), col sign (+,-,-,+))
//   dP = sum over pairs (i, i^12): rows 0<->3 and 1<->2, same column
// Outputs: per-kernel 3x2 linear map of (D2/S2, dP/S2); coefficients depend
// only on U3 of qubit 0 (wires-1..3 unitary cancels: real input, wire-0 obs).
//
// Two vertically adjacent patches per thread, ALL 12 row-loads hoisted to the
// top (MLP=12), both computes, then 24 stores. 8192 warps -> single wave.

__global__ __launch_bounds__(128, 14) void qconv_kernel(const float* __restrict__ x,
                                                        const float* __restrict__ w,
                                                        float* __restrict__ out) {
    __shared__ float4 cfT[6];   // cfT[2c+0]=Dl-coef, cfT[2c+1]=dd-coef, kernels 0..3
    const int tid = threadIdx.y * 32 + threadIdx.x;
    if (tid < 4) {
        const int k = tid;
        float th = w[k * 12 + 0], ph = w[k * 12 + 1], om = w[k * 12 + 2];
        float st, ct, spo, cpo, smp, cmp, sp, cp, som, com_;
        sincosf(th, &st, &ct);
        sincosf(ph, &sp, &cp);
        sincosf(ph + om, &spo, &cpo);
        sincosf(om - ph, &smp, &cmp);
        sincosf(om, &som, &com_);
        float c2 = 0.5f * (1.0f + ct);
        float s2 = 0.5f * (1.0f - ct);
        float* cfs = reinterpret_cast<float*>(cfT);
        cfs[0 * 4 + k] = st * cp;                       // ex: Dl
        cfs[1 * 4 + k] = 2.0f * (c2 * cpo - s2 * cmp);  // ex: dd
        cfs[2 * 4 + k] = st * sp;                       // ey: Dl
        cfs[3 * 4 + k] = 2.0f * (c2 * spo + s2 * smp);  // ey: dd
        cfs[4 * 4 + k] = ct;                            // ez: Dl
        cfs[5 * 4 + k] = -2.0f * st * com_;             // ez: dd
    }
    __syncthreads();

    const int lane = threadIdx.x;
    if (lane >= WO) return;                         // keep loads in-bounds

    const int pair = blockIdx.y * 4 + threadIdx.y;  // 0..15 -> patch rows (2p,2p+1)
    const bool hasB = (pair < 15);                  // pair 15: only ho=30 valid
    const int b = blockIdx.z;

    // input rows 4*pair .. 4*pair+5 ; columns [2*lane .. 2*lane+3]
    const float* base = x + (size_t)b * (HW * HW) + (size_t)(4 * pair) * HW + lane * 2;

    // ---- all loads up-front ----
    float2 u0 = *reinterpret_cast<const float2*>(base);
    float2 v0 = *reinterpret_cast<const float2*>(base + 2);
    float2 u1 = *reinterpret_cast<const float2*>(base + HW);
    float2 v1 = *reinterpret_cast<const float2*>(base + HW + 2);
    float2 u2 = *reinterpret_cast<const float2*>(base + 2 * HW);
    float2 v2 = *reinterpret_cast<const float2*>(base + 2 * HW + 2);
    float2 u3 = *reinterpret_cast<const float2*>(base + 3 * HW);
    float2 v3 = *reinterpret_cast<const float2*>(base + 3 * HW + 2);
    float2 u4 = make_float2(0.f, 0.f), v4 = u4, u5 = u4, v5 = u4;
    if (hasB) {
        u4 = *reinterpret_cast<const float2*>(base + 4 * HW);
        v4 = *reinterpret_cast<const float2*>(base + 4 * HW + 2);
        u5 = *reinterpret_cast<const float2*>(base + 5 * HW);
        v5 = *reinterpret_cast<const float2*>(base + 5 * HW + 2);
    }

    // per-row invariants: s_r = |row|^2, d_r = x^2 - y^2 - z^2 + w^2
    float s0 = u0.x * u0.x + u0.y * u0.y + v0.x * v0.x + v0.y * v0.y;
    float s1 = u1.x * u1.x + u1.y * u1.y + v1.x * v1.x + v1.y * v1.y;
    float s2r = u2.x * u2.x + u2.y * u2.y + v2.x * v2.x + v2.y * v2.y;
    float s3 = u3.x * u3.x + u3.y * u3.y + v3.x * v3.x + v3.y * v3.y;
    float d0 = u0.x * u0.x - u0.y * u0.y - v0.x * v0.x + v0.y * v0.y;
    float d1 = u1.x * u1.x - u1.y * u1.y - v1.x * v1.x + v1.y * v1.y;
    float d2 = u2.x * u2.x - u2.y * u2.y - v2.x * v2.x + v2.y * v2.y;
    float d3 = u3.x * u3.x - u3.y * u3.y - v3.x * v3.x + v3.y * v3.y;

    // ---- patch A: rows 0..3 ----
    float SA = s0 + s1 + s2r + s3;
    float DA = d0 - d1 + d2 - d3;
    float PA = u0.x * u3.x + u0.y * u3.y + v0.x * v3.x + v0.y * v3.y
             + u1.x * u2.x + u1.y * u2.y + v1.x * v2.x + v1.y * v2.y;
    float invA = 1.0f / SA;
    float DlA = DA * invA, ddA = PA * invA;

    // ---- patch B: rows 2..5 ----
    float DlB = 0.f, ddB = 0.f;
    if (hasB) {
        float s4 = u4.x * u4.x + u4.y * u4.y + v4.x * v4.x + v4.y * v4.y;
        float s5 = u5.x * u5.x + u5.y * u5.y + v5.x * v5.x + v5.y * v5.y;
        float d4 = u4.x * u4.x - u4.y * u4.y - v4.x * v4.x + v4.y * v4.y;
        float d5 = u5.x * u5.x - u5.y * u5.y - v5.x * v5.x + v5.y * v5.y;
        float SB = s2r + s3 + s4 + s5;
        float DB = d2 - d3 + d4 - d5;
        float PB = u2.x * u5.x + u2.y * u5.y + v2.x * v5.x + v2.y * v5.y
                 + u3.x * u4.x + u3.y * u4.y + v3.x * v4.x + v3.y * v4.y;
        float invB = 1.0f / SB;
        DlB = DB * invB;
        ddB = PB * invB;
    }

    // ---- epilogue: 24 stores (12 per patch) ----
    const size_t obase = (size_t)b * 12 * PLANE + (size_t)(2 * pair) * WO + lane;
#pragma unroll
    for (int c = 0; c < 3; ++c) {
        float4 a = cfT[2 * c + 0];
        float4 g = cfT[2 * c + 1];
        out[obase + (size_t)(0 + c) * PLANE] = a.x * DlA + g.x * ddA;
        out[obase + (size_t)(3 + c) * PLANE] = a.y * DlA + g.y * ddA;
        out[obase + (size_t)(6 + c) * PLANE] = a.z * DlA + g.z * ddA;
        out[obase + (size_t)(9 + c) * PLANE] = a.w * DlA + g.w * ddA;
        if (hasB) {
            out[obase + WO + (size_t)(0 + c) * PLANE] = a.x * DlB + g.x * ddB;
            out[obase + WO + (size_t)(3 + c) * PLANE] = a.y * DlB + g.y * ddB;
            out[obase + WO + (size_t)(6 + c) * PLANE] = a.z * DlB + g.z * ddB;
            out[obase + WO + (size_t)(9 + c) * PLANE] = a.w * DlB + g.w * ddB;
        }
    }
}

extern "C" void kernel_launch(void* const* d_in, const int* in_sizes, int n_in,
                              void* d_out, int out_size) {
    const float* x = (const float*)d_in[0];
    const float* w = (const float*)d_in[1];
    if (n_in >= 2 && in_sizes[0] == 48) {  // robustness: weights listed first
        x = (const float*)d_in[1];
        w = (const float*)d_in[0];
    }
    float* out = (float*)d_out;

    dim3 blk(32, 4, 1);
    dim3 grd(1, 4, BATCH);   // 4 y-blocks x 4 pairs = 16 pairs cover HO=31
    qconv_kernel<<<grd, blk>>>(x, w, out);
}